// round 7
// baseline (speedup 1.0000x reference)
#include <cuda_runtime.h>
#include <cuda_fp16.h>
#include <cstdint>

#define B_ 8
#define C_ 256
#define D_ 32
#define N_ 4096
#define QTILE 64
#define KTILE 64
#define NTILES (N_ / KTILE)
#define THREADS 256

// smem byte offsets
#define SM_Q  0                         // Q hi/lo: 2 x 64 x 64B (SW64) = 8192
#define SM_K  8192                      // K[buf][hl]: 4 x 4096 (SW64)  = 16384
#define SM_V  24576                     // V[buf]: 2 x 32768 (SW128)    = 65536
#define SM_TOTAL 90112

// ---------------------------------------------------------------------------
// scratch (allocation-free rule: device globals)
// q,k: [B][N][32] fp16 hi/lo;  v: [B][C][N] fp16
// ---------------------------------------------------------------------------
__device__ __half g_qh[(size_t)B_ * N_ * D_];
__device__ __half g_ql[(size_t)B_ * N_ * D_];
__device__ __half g_kh[(size_t)B_ * N_ * D_];
__device__ __half g_kl[(size_t)B_ * N_ * D_];
__device__ __half g_v [(size_t)B_ * C_ * N_];

typedef unsigned long long ull;

__device__ __forceinline__ uint32_t smem_u32(const void* p) {
    uint32_t a;
    asm("{ .reg .u64 t; cvta.to.shared.u64 t, %1; cvt.u32.u64 %0, t; }" : "=r"(a) : "l"(p));
    return a;
}
__device__ __forceinline__ void ldsm4(uint32_t* r, uint32_t addr) {
    asm volatile("ldmatrix.sync.aligned.m8n8.x4.shared.b16 {%0,%1,%2,%3}, [%4];"
                 : "=r"(r[0]), "=r"(r[1]), "=r"(r[2]), "=r"(r[3]) : "r"(addr));
}
__device__ __forceinline__ void mma_f16(float* c, const uint32_t* a, uint32_t b0, uint32_t b1) {
    asm volatile("mma.sync.aligned.m16n8k16.row.col.f32.f16.f16.f32 "
                 "{%0,%1,%2,%3}, {%4,%5,%6,%7}, {%8,%9}, {%0,%1,%2,%3};"
                 : "+f"(c[0]), "+f"(c[1]), "+f"(c[2]), "+f"(c[3])
                 : "r"(a[0]), "r"(a[1]), "r"(a[2]), "r"(a[3]), "r"(b0), "r"(b1));
}
__device__ __forceinline__ void cpa16(uint32_t dst, const void* src) {
    asm volatile("cp.async.cg.shared.global [%0], [%1], 16;" :: "r"(dst), "l"(src));
}
#define CP_COMMIT() asm volatile("cp.async.commit_group;" ::: "memory")
#define CP_WAIT(n)  asm volatile("cp.async.wait_group %0;" :: "n"(n) : "memory")

// swizzles: 64B rows (Q/K) and 128B rows (V)
__device__ __forceinline__ uint32_t sw64(int row, int u)  { return row * 64  + ((u ^ ((row >> 1) & 3)) << 4); }
__device__ __forceinline__ uint32_t sw128(int row, int u) { return row * 128 + ((u ^ (row & 7)) << 4); }

// ldmatrix x4 address helpers
__device__ __forceinline__ uint32_t a64(uint32_t base, int row0, int k16, int lane) {
    int lr = lane & 7, grp = lane >> 3;
    return base + sw64(row0 + lr + (grp & 1) * 8, k16 + (grp >> 1));
}
__device__ __forceinline__ uint32_t b64(uint32_t base, int row0, int k16, int lane) {
    int lr = lane & 7, grp = lane >> 3;
    return base + sw64(row0 + lr + (grp >> 1) * 8, k16 + (grp & 1));
}
__device__ __forceinline__ uint32_t b128(uint32_t base, int row0, int k16, int lane) {
    int lr = lane & 7, grp = lane >> 3;
    return base + sw128(row0 + lr + (grp >> 1) * 8, k16 + (grp & 1));
}

// f32x2 helpers (qkv)
__device__ __forceinline__ void ffma2(ull& d, ull a, ull b) {
    asm("fma.rn.f32x2 %0, %1, %2, %0;" : "+l"(d) : "l"(a), "l"(b));
}
__device__ __forceinline__ ull pack2(float lo, float hi) {
    ull r; asm("mov.b64 %0, {%1, %2};" : "=l"(r) : "f"(lo), "f"(hi)); return r;
}
__device__ __forceinline__ void unpack2(ull p, float& lo, float& hi) {
    asm("mov.b64 {%0, %1}, %2;" : "=f"(lo), "=f"(hi) : "l"(p));
}
__device__ __forceinline__ uint32_t h2pack(float a, float b) {
    __half2 h = __floats2half2_rn(a, b);
    return *reinterpret_cast<uint32_t*>(&h);
}

// ---------------------------------------------------------------------------
// QKV projection (f32x2 SIMT GEMM, outputs fp16: q/k hi+lo, v single)
// ---------------------------------------------------------------------------
__global__ __launch_bounds__(256) void qkv_kernel(
    const float* __restrict__ x,
    const float* __restrict__ Wq, const float* __restrict__ bq,
    const float* __restrict__ Wk, const float* __restrict__ bk,
    const float* __restrict__ Wv, const float* __restrict__ bv)
{
    __shared__ float Wt[16][66];
    __shared__ float Xt[16][132];

    const int b    = blockIdx.z;
    const int row0 = blockIdx.y * 64;
    const int n0   = blockIdx.x * 128;
    const int t    = threadIdx.x;
    const int tx   = t & 31;
    const int ty   = t >> 5;

    ull acc2[4][4];
#pragma unroll
    for (int i2 = 0; i2 < 4; i2++)
#pragma unroll
        for (int j = 0; j < 4; j++) acc2[i2][j] = 0ULL;

    const float* xb = x + (size_t)b * C_ * N_;

    for (int k0 = 0; k0 < C_; k0 += 16) {
        {
            int r = t >> 2, kk4 = (t & 3) << 2, rg = row0 + r;
            const float* wrow;
            if (rg < 32)      wrow = Wq + (size_t)rg * C_;
            else if (rg < 64) wrow = Wk + (size_t)(rg - 32) * C_;
            else              wrow = Wv + (size_t)(rg - 64) * C_;
            float4 w4 = *(const float4*)(wrow + k0 + kk4);
            Wt[kk4 + 0][r] = w4.x; Wt[kk4 + 1][r] = w4.y;
            Wt[kk4 + 2][r] = w4.z; Wt[kk4 + 3][r] = w4.w;
        }
#pragma unroll
        for (int it = 0; it < 2; it++) {
            int flat = it * 256 + t;
            int kk = flat >> 5, nn4 = (flat & 31) << 2;
            *(float4*)&Xt[kk][nn4] = *(const float4*)(xb + (size_t)(k0 + kk) * N_ + n0 + nn4);
        }
        __syncthreads();
#pragma unroll
        for (int kk = 0; kk < 16; kk++) {
            float4 xv = *(float4*)&Xt[kk][tx << 2];
            ull bx = pack2(xv.x, xv.x), by = pack2(xv.y, xv.y);
            ull bz = pack2(xv.z, xv.z), bw = pack2(xv.w, xv.w);
#pragma unroll
            for (int i2 = 0; i2 < 4; i2++) {
                float2 w2 = *(float2*)&Wt[kk][(ty << 3) + (i2 << 1)];
                ull a2 = pack2(w2.x, w2.y);
                ffma2(acc2[i2][0], a2, bx);
                ffma2(acc2[i2][1], a2, by);
                ffma2(acc2[i2][2], a2, bz);
                ffma2(acc2[i2][3], a2, bw);
            }
        }
        __syncthreads();
    }

    float acc[8][4];
#pragma unroll
    for (int i2 = 0; i2 < 4; i2++)
#pragma unroll
        for (int j = 0; j < 4; j++)
            unpack2(acc2[i2][j], acc[i2 * 2][j], acc[i2 * 2 + 1][j]);

#pragma unroll
    for (int i = 0; i < 8; i++) {
        int rg = row0 + (ty << 3) + i;
        if (rg < 64) {
            const bool isq = (rg < 32);
            const int  d    = isq ? rg : rg - 32;
            const float bias = isq ? bq[rg] : bk[rg - 32];
            __half* dh = isq ? g_qh : g_kh;
            __half* dl = isq ? g_ql : g_kl;
#pragma unroll
            for (int jj = 0; jj < 4; jj++) {
                int n = n0 + (tx << 2) + jj;
                float v = acc[i][jj] + bias;
                __half h = __float2half_rn(v);
                __half l = __float2half_rn(v - __half2float(h));
                size_t o = ((size_t)b * N_ + n) * D_ + d;
                dh[o] = h; dl[o] = l;
            }
        } else {
            int c = rg - 64;
            float bias = bv[c];
            __half2 v01 = __floats2half2_rn(acc[i][0] + bias, acc[i][1] + bias);
            __half2 v23 = __floats2half2_rn(acc[i][2] + bias, acc[i][3] + bias);
            size_t o = ((size_t)b * C_ + c) * (size_t)N_ + n0 + (tx << 2);
            *(uint2*)(g_v + o) = make_uint2(*(uint32_t*)&v01, *(uint32_t*)&v23);
        }
    }
}

// ---------------------------------------------------------------------------
// FA2-style flash attention, register-resident P.
// 1 CTA per (batch, 64-q tile), 256 thr, 2 CTAs/SM.
// Warp w: qs = (w>>1)*16 q-rows (full 64-j width), ch = (w&1)*128 channels.
// Softmax fully warp-local; quantized online max (multiples of 8);
// P fragment built in registers from QK accumulator (no smem round-trip).
// ---------------------------------------------------------------------------
__global__ __launch_bounds__(THREADS, 2) void attn_kernel(
    const float* __restrict__ x, const float* __restrict__ gamma_p,
    float* __restrict__ out)
{
    extern __shared__ char smem[];
    const uint32_t sb = smem_u32(smem);
    const int t    = threadIdx.x;
    const int w    = t >> 5;
    const int lane = t & 31;
    const int g    = lane >> 2;
    const int tig  = lane & 3;
    const int b    = blockIdx.y;
    const int q0   = blockIdx.x * QTILE;
    const int qs   = (w >> 1) * 16;
    const int ch   = (w & 1) * 128;

    const __half* qhp = g_qh + (size_t)b * N_ * D_;
    const __half* qlp = g_ql + (size_t)b * N_ * D_;
    const __half* khp = g_kh + (size_t)b * N_ * D_;
    const __half* klp = g_kl + (size_t)b * N_ * D_;
    const __half* vp  = g_v  + (size_t)b * C_ * (size_t)N_;

    // prefetch tile 0 (K hi/lo + V) into buf 0
#pragma unroll
    for (int it = 0; it < 2; it++) {
        int chunk = it * THREADS + t;
        int hl = chunk >> 8, idx = chunk & 255, row = idx >> 2, u = idx & 3;
        const __half* src = (hl ? klp : khp) + (size_t)row * D_ + u * 8;
        cpa16(sb + SM_K + hl * 4096 + sw64(row, u), src);
    }
#pragma unroll
    for (int it = 0; it < 8; it++) {
        int chunk = it * THREADS + t;
        int row = chunk >> 3, u = chunk & 7;
        cpa16(sb + SM_V + sw128(row, u), vp + (size_t)row * N_ + u * 8);
    }
    CP_COMMIT();

    // Q tile (hi/lo) plain load
#pragma unroll
    for (int it = 0; it < 2; it++) {
        int chunk = it * THREADS + t;
        int hl = chunk >> 8, idx = chunk & 255, row = idx >> 2, u = idx & 3;
        const __half* src = (hl ? qlp : qhp) + (size_t)(q0 + row) * D_ + u * 8;
        *(uint4*)(smem + SM_Q + hl * 4096 + sw64(row, u)) = *(const uint4*)src;
    }

    float o[16][4];
#pragma unroll
    for (int n = 0; n < 16; n++) { o[n][0]=0.f; o[n][1]=0.f; o[n][2]=0.f; o[n][3]=0.f; }
    float lacc0 = 0.f, lacc1 = 0.f;
    float mold0 = -1e30f, mold1 = -1e30f;

    __syncthreads();   // Q visible (also joins prefetch issue)

    for (int tile = 0; tile < NTILES; tile++) {
        const int buf = tile & 1;
        // prefetch next tile into other buffer (freed: consumers of tile-1 done
        // at the barrier that ended the previous iteration)
        if (tile + 1 < NTILES) {
            const int jn = (tile + 1) * KTILE, bn = (tile + 1) & 1;
#pragma unroll
            for (int it = 0; it < 2; it++) {
                int chunk = it * THREADS + t;
                int hl = chunk >> 8, idx = chunk & 255, row = idx >> 2, u = idx & 3;
                const __half* src = (hl ? klp : khp) + (size_t)(jn + row) * D_ + u * 8;
                cpa16(sb + SM_K + (bn * 2 + hl) * 4096 + sw64(row, u), src);
            }
#pragma unroll
            for (int it = 0; it < 8; it++) {
                int chunk = it * THREADS + t;
                int row = chunk >> 3, u = chunk & 7;
                cpa16(sb + SM_V + bn * 32768 + sw128(row, u), vp + (size_t)row * N_ + jn + u * 8);
            }
            CP_COMMIT();
            CP_WAIT(1);
        } else {
            CP_WAIT(0);
        }
        __syncthreads();   // tile's K/V visible to all

        // ---- S = Q K^T : warp's 16q x 64j, 3-term fp16 split ----
        float s[8][4];
#pragma unroll
        for (int n = 0; n < 8; n++) { s[n][0]=0.f; s[n][1]=0.f; s[n][2]=0.f; s[n][3]=0.f; }
#pragma unroll
        for (int kb = 0; kb < 2; kb++) {
            uint32_t qh4[4], ql4[4];
            ldsm4(qh4, a64(sb + SM_Q,        qs, kb * 2, lane));
            ldsm4(ql4, a64(sb + SM_Q + 4096, qs, kb * 2, lane));
#pragma unroll
            for (int i = 0; i < 4; i++) {
                uint32_t kh4[4], kl4[4];
                ldsm4(kh4, b64(sb + SM_K + (buf * 2 + 0) * 4096, i * 16, kb * 2, lane));
                ldsm4(kl4, b64(sb + SM_K + (buf * 2 + 1) * 4096, i * 16, kb * 2, lane));
                mma_f16(s[2*i],   qh4, kh4[0], kh4[1]);
                mma_f16(s[2*i+1], qh4, kh4[2], kh4[3]);
                mma_f16(s[2*i],   qh4, kl4[0], kl4[1]);
                mma_f16(s[2*i+1], qh4, kl4[2], kl4[3]);
                mma_f16(s[2*i],   ql4, kh4[0], kh4[1]);
                mma_f16(s[2*i+1], ql4, kh4[2], kh4[3]);
            }
        }

        // ---- warp-local row max (quantized to multiples of 8) ----
        float m0 = -1e30f, m1 = -1e30f;
#pragma unroll
        for (int n = 0; n < 8; n++) {
            m0 = fmaxf(m0, fmaxf(s[n][0], s[n][1]));
            m1 = fmaxf(m1, fmaxf(s[n][2], s[n][3]));
        }
        m0 = fmaxf(m0, __shfl_xor_sync(0xffffffffu, m0, 1));
        m0 = fmaxf(m0, __shfl_xor_sync(0xffffffffu, m0, 2));
        m1 = fmaxf(m1, __shfl_xor_sync(0xffffffffu, m1, 1));
        m1 = fmaxf(m1, __shfl_xor_sync(0xffffffffu, m1, 2));
        float mq0 = 8.f * ceilf(m0 * 0.125f);
        float mq1 = 8.f * ceilf(m1 * 0.125f);
        float mn0 = fmaxf(mold0, mq0);
        float mn1 = fmaxf(mold1, mq1);
        bool upd = (mn0 > mold0) || (mn1 > mold1);
        if (__any_sync(0xffffffffu, upd)) {
            float al0 = __expf(mold0 - mn0);
            float al1 = __expf(mold1 - mn1);
#pragma unroll
            for (int n = 0; n < 16; n++) {
                o[n][0] *= al0; o[n][1] *= al0;
                o[n][2] *= al1; o[n][3] *= al1;
            }
            lacc0 *= al0; lacc1 *= al1;
            mold0 = mn0; mold1 = mn1;
        }

        // ---- exp, l accumulate, build P A-fragments in registers ----
        uint32_t p[4][4];
#pragma unroll
        for (int n = 0; n < 8; n++) {
            float e0 = __expf(s[n][0] - mold0);
            float e1 = __expf(s[n][1] - mold0);
            float e2 = __expf(s[n][2] - mold1);
            float e3 = __expf(s[n][3] - mold1);
            lacc0 += e0 + e1;
            lacc1 += e2 + e3;
            int kb = n >> 1, hi = (n & 1) << 1;   // n even -> regs 0,1; odd -> 2,3
            p[kb][hi]     = h2pack(e0, e1);
            p[kb][hi + 1] = h2pack(e2, e3);
        }

        // ---- O += P V^T : warp's 16q x 128c, single fp16 term ----
#pragma unroll
        for (int kb = 0; kb < 4; kb++) {
#pragma unroll
            for (int i = 0; i < 8; i++) {
                uint32_t v4[4];
                ldsm4(v4, b128(sb + SM_V + buf * 32768, ch + i * 16, kb * 2, lane));
                mma_f16(o[2*i],   p[kb], v4[0], v4[1]);
                mma_f16(o[2*i+1], p[kb], v4[2], v4[3]);
            }
        }
        __syncthreads();   // all warps done with this tile's buffers
    }

    // ---- finalize l (quad sum), epilogue out = gamma*O/l + x ----
    lacc0 += __shfl_xor_sync(0xffffffffu, lacc0, 1);
    lacc0 += __shfl_xor_sync(0xffffffffu, lacc0, 2);
    lacc1 += __shfl_xor_sync(0xffffffffu, lacc1, 1);
    lacc1 += __shfl_xor_sync(0xffffffffu, lacc1, 2);
    const float li0 = 1.f / lacc0;
    const float li1 = 1.f / lacc1;
    const float gma = *gamma_p;
    const int i0 = q0 + qs + g;
    const int i1 = i0 + 8;
#pragma unroll
    for (int n = 0; n < 16; n++) {
        int c = ch + n * 8 + tig * 2;
        size_t base0 = ((size_t)b * C_ + c) * (size_t)N_;
        size_t base1 = base0 + N_;
        out[base0 + i0] = gma * (o[n][0] * li0) + x[base0 + i0];
        out[base1 + i0] = gma * (o[n][1] * li0) + x[base1 + i0];
        out[base0 + i1] = gma * (o[n][2] * li1) + x[base0 + i1];
        out[base1 + i1] = gma * (o[n][3] * li1) + x[base1 + i1];
    }
}

extern "C" void kernel_launch(void* const* d_in, const int* in_sizes, int n_in,
                              void* d_out, int out_size) {
    const float* x  = (const float*)d_in[0];
    const float* Wq = (const float*)d_in[1];
    const float* bq = (const float*)d_in[2];
    const float* Wk = (const float*)d_in[3];
    const float* bk = (const float*)d_in[4];
    const float* Wv = (const float*)d_in[5];
    const float* bv = (const float*)d_in[6];
    const float* gm = (const float*)d_in[7];
    float* out = (float*)d_out;

    cudaFuncSetAttribute(attn_kernel, cudaFuncAttributeMaxDynamicSharedMemorySize, SM_TOTAL);

    qkv_kernel<<<dim3(32, 5, 8), 256>>>(x, Wq, bq, Wk, bk, Wv, bv);
    attn_kernel<<<dim3(N_ / QTILE, B_), THREADS, SM_TOTAL>>>(x, gm, out);
}